// round 1
// baseline (speedup 1.0000x reference)
#include <cuda_runtime.h>

#define NN 32
#define DD 128
#define SS 128
#define MM 64
#define IJ (MM * MM)
#define BASIS 5

// Scratch (static __device__ — no allocations allowed)
__device__ float g_mc[NN * DD * MM];   // mean over rows i  -> [n][d][j]
__device__ float g_dg[NN * DD * MM];   // diagonal          -> [n][d][t]
__device__ float g_md[NN * DD];        // mean of diag
__device__ float g_ma[NN * DD];        // mean of all
__device__ float g_c2[DD * SS];        // packed coeffs[d][s][1], row-major [d][s]
__device__ float g_V [NN * SS * MM];   // V[n][s][t]
__device__ float g_B [NN * SS];        // B[n][s] (includes bias)

// ---------------------------------------------------------------------------
// Kernel 0: pack the b=1 coeff plane contiguously for the GEMM
// ---------------------------------------------------------------------------
__global__ void pack_coeffs_kernel(const float* __restrict__ coeffs) {
    int idx = blockIdx.x * blockDim.x + threadIdx.x;  // over D*S
    if (idx < DD * SS) g_c2[idx] = coeffs[idx * BASIS + 1];
}

// ---------------------------------------------------------------------------
// Kernel 1: per-(n,d) reductions. One block per (n,d), 64 threads (one per col)
// ---------------------------------------------------------------------------
__global__ __launch_bounds__(64) void reduce_kernel(const float* __restrict__ X) {
    int nd = blockIdx.x;
    const float* x = X + (size_t)nd * IJ;
    int j = threadIdx.x;

    float s = 0.f;
#pragma unroll 8
    for (int i = 0; i < MM; i++) s += x[i * MM + j];   // coalesced per row
    float mc = s * (1.0f / MM);
    float dg = x[j * MM + j];

    g_mc[nd * MM + j] = mc;
    g_dg[nd * MM + j] = dg;

    __shared__ float sh1[64], sh2[64];
    sh1[j] = dg;
    sh2[j] = mc;
    __syncthreads();
#pragma unroll
    for (int off = 32; off > 0; off >>= 1) {
        if (j < off) { sh1[j] += sh1[j + off]; sh2[j] += sh2[j + off]; }
        __syncthreads();
    }
    if (j == 0) {
        g_md[nd] = sh1[0] * (1.0f / MM);
        g_ma[nd] = sh2[0] * (1.0f / MM);
    }
}

// ---------------------------------------------------------------------------
// Kernel 2: V[n,s,t] and B[n,s]. Grid (S, N), 64 threads (t).
// ---------------------------------------------------------------------------
__global__ __launch_bounds__(64) void vb_kernel(const float* __restrict__ coeffs,
                                                const float* __restrict__ bias) {
    int s = blockIdx.x, n = blockIdx.y;
    int t = threadIdx.x;
    const float* mc = g_mc + (size_t)n * DD * MM;
    const float* dg = g_dg + (size_t)n * DD * MM;

    float v = 0.f;
#pragma unroll 4
    for (int d = 0; d < DD; d++) {
        const float* c = coeffs + (size_t)(d * SS + s) * BASIS;
        v += c[0] * mc[d * MM + t] + c[2] * dg[d * MM + t];
    }
    g_V[(size_t)(n * SS + s) * MM + t] = v;

    if (t == 0) {
        float bb = 0.f;
        for (int d = 0; d < DD; d++) {
            const float* c = coeffs + (size_t)(d * SS + s) * BASIS;
            bb += c[3] * g_md[n * DD + d] + c[4] * g_ma[n * DD + d];
        }
        g_B[n * SS + s] = bb + bias[s];
    }
}

// ---------------------------------------------------------------------------
// Kernel 3: main batched GEMM + epilogue.
//   out[n,s,i,j] = sum_d c2[d,s] * X[n,d,i,j] + 0.5*(V[n,s,i]+V[n,s,j]) + B[n,s]
// Block computes [S=128] x [64 j's of row i]. Grid (i=64, n=32). 256 threads.
// Thread microtile: 8 (s) x 4 (j).
// ---------------------------------------------------------------------------
__global__ __launch_bounds__(256) void main_gemm_kernel(const float* __restrict__ X,
                                                        float* __restrict__ out) {
    const int ti = blockIdx.x;   // row index i (tile of 64 consecutive ij = fixed i)
    const int n  = blockIdx.y;

    __shared__ float As[16][SS];  // [kk][s]  coeffs slab   (8 KB)
    __shared__ float Bs[16][MM];  // [kk][j]  X slab        (4 KB)

    const int tid = threadIdx.x;
    const int tx = tid & 15;     // j-group: j = tx*4 .. +3
    const int ty = tid >> 4;     // s-group: s = ty*8 .. +7

    float acc[8][4];
#pragma unroll
    for (int m = 0; m < 8; m++)
#pragma unroll
        for (int q = 0; q < 4; q++) acc[m][q] = 0.f;

    const float* xbase = X + ((size_t)n * DD) * IJ + (size_t)ti * MM;

    const int kkL = tid >> 4, jfL = tid & 15;   // B-slab load coords

    for (int k0 = 0; k0 < DD; k0 += 16) {
        __syncthreads();
        // load coeff slab: 16*128 contiguous floats = 512 float4, 2 per thread
        {
            const float4* src = (const float4*)(g_c2 + k0 * SS);
            float4* dst = (float4*)(&As[0][0]);
            dst[tid]       = src[tid];
            dst[tid + 256] = src[tid + 256];
        }
        // load X slab: 16 rows x 64 floats; row kk at stride IJ
        {
            const float4* srcb = (const float4*)(xbase + (size_t)(k0 + kkL) * IJ);
            ((float4*)(&Bs[kkL][0]))[jfL] = srcb[jfL];
        }
        __syncthreads();

#pragma unroll
        for (int kk = 0; kk < 16; kk++) {
            float4 a0 = *(const float4*)&As[kk][ty * 8];
            float4 a1 = *(const float4*)&As[kk][ty * 8 + 4];
            float4 b0 = *(const float4*)&Bs[kk][tx * 4];
            float a[8] = {a0.x, a0.y, a0.z, a0.w, a1.x, a1.y, a1.z, a1.w};
            float b[4] = {b0.x, b0.y, b0.z, b0.w};
#pragma unroll
            for (int m = 0; m < 8; m++)
#pragma unroll
                for (int q = 0; q < 4; q++) acc[m][q] += a[m] * b[q];
        }
    }

    // epilogue
    const int j0 = tx * 4;
#pragma unroll
    for (int m = 0; m < 8; m++) {
        int s = ty * 8 + m;
        const float* vrow = g_V + (size_t)(n * SS + s) * MM;
        float base = 0.5f * vrow[ti] + g_B[n * SS + s];
        float4 r;
        r.x = acc[m][0] + base + 0.5f * vrow[j0 + 0];
        r.y = acc[m][1] + base + 0.5f * vrow[j0 + 1];
        r.z = acc[m][2] + base + 0.5f * vrow[j0 + 2];
        r.w = acc[m][3] + base + 0.5f * vrow[j0 + 3];
        *(float4*)&out[(((size_t)n * SS + s) * MM + ti) * MM + j0] = r;
    }
}

// ---------------------------------------------------------------------------
extern "C" void kernel_launch(void* const* d_in, const int* in_sizes, int n_in,
                              void* d_out, int out_size) {
    const float* X      = (const float*)d_in[0];  // [32,128,64,64]
    const float* coeffs = (const float*)d_in[1];  // [128,128,5]
    const float* bias   = (const float*)d_in[2];  // [1,128,1,1]
    float* out = (float*)d_out;

    pack_coeffs_kernel<<<(DD * SS + 255) / 256, 256>>>(coeffs);
    reduce_kernel<<<NN * DD, 64>>>(X);
    vb_kernel<<<dim3(SS, NN), 64>>>(coeffs, bias);
    main_gemm_kernel<<<dim3(MM, NN), 256>>>(X, out);
}